// round 14
// baseline (speedup 1.0000x reference)
#include <cuda_runtime.h>
#include <math.h>

#define BB 32
#define TT 1024
#define II 512
#define HH 512
#define G4 2048      // 4*H
#define GRID_P 128   // persistent CTAs (<=148 -> co-resident, deadlock-free)

typedef unsigned long long u64t;

// ---- packed fp32x2 helpers (Blackwell FFMA2) ----
__device__ __forceinline__ u64t ffma2(u64t a, u64t b, u64t c) {
    u64t d;
    asm("fma.rn.f32x2 %0, %1, %2, %3;" : "=l"(d) : "l"(a), "l"(b), "l"(c));
    return d;
}
__device__ __forceinline__ u64t pack2(float x, float y) {
    u64t d;
    asm("mov.b64 %0, {%1, %2};" : "=l"(d) : "f"(x), "f"(y));
    return d;
}
__device__ __forceinline__ float2 unpack2(u64t v) {
    float2 r;
    asm("mov.b64 {%0, %1}, %2;" : "=f"(r.x), "=f"(r.y) : "l"(v));
    return r;
}
// L2-coherent 16B load (L1 is stale across CTAs; REQUIRED for h double-buffer)
__device__ __forceinline__ void ldcg2(const float* p, u64t& a, u64t& b) {
    asm volatile("ld.global.cg.v2.u64 {%0,%1}, [%2];" : "=l"(a), "=l"(b) : "l"(p));
}

// ---------------- scratch (static device globals; no allocation) ----------------
__device__ float    g_xT[(size_t)TT * II * BB];     // x transposed [t][k][b]  64 MB
__device__ float    g_hT[2][HH * BB];               // double-buffered h^T [k][b]
__device__ unsigned g_bar_count;
__device__ unsigned g_bar_phase;

// ---------------- Kernel 0: transpose x -> xT[t][k][b]; init hT/barrier ---------
#define XPAD 520
__global__ __launch_bounds__(512) void prep_kernel(
    const float* __restrict__ x, const float* __restrict__ h0)
{
    extern __shared__ float xs[];          // [32][XPAD]
    const int t   = blockIdx.x;
    const int tid = threadIdx.x;

    // load x[b][t][0..511] coalesced -> SMEM [b][k]
#pragma unroll
    for (int i = 0; i < 8; i++) {
        int idx = tid + i * 512;           // 0..4095 float4
        int b   = idx >> 7;                // 128 float4 per batch row
        int kc  = idx & 127;
        float4 v = *(const float4*)(x + ((size_t)b * TT + t) * 512 + kc * 4);
        *(float4*)&xs[b * XPAD + kc * 4] = v;
    }
    __syncthreads();

    // store xT[t][k][b] coalesced (gather transpose from SMEM)
    float* dst = g_xT + (size_t)t * (512 * 32);
#pragma unroll
    for (int i = 0; i < 8; i++) {
        int idx = tid + i * 512;           // 0..4095 float4 of output
        int k   = idx >> 3;                // 8 float4 per k row
        int bq  = idx & 7;
        float4 v;
        v.x = xs[(bq * 4 + 0) * XPAD + k];
        v.y = xs[(bq * 4 + 1) * XPAD + k];
        v.z = xs[(bq * 4 + 2) * XPAD + k];
        v.w = xs[(bq * 4 + 3) * XPAD + k];
        *(float4*)(dst + k * 32 + bq * 4) = v;
    }

    if (t == 0) {
        for (int i = tid; i < BB * HH; i += 512) {
            int b = i >> 9;
            int j = i & 511;
            g_hT[0][j * BB + b] = h0[i];
        }
        if (tid == 0) { g_bar_count = 0; g_bar_phase = 0; }
    }
}

// ---------------- fused GEMM slice (round-10 proven inner loop) ------------------
// lane_src: [k][32b] base + kb*32 + bq*4 ; wrow: wbase + kb*16 + gco*4 ;
// ps: partial base + w*512. acc[p][bb]: gate-col pair (gco*4+2p,+1) x batch bq*4+bb.
__device__ __forceinline__ void gemm_slice(
    const float* __restrict__ lane_src, const float* __restrict__ wrow,
    float* __restrict__ ps, const int gco, const int bq)
{
    u64t acc[2][4];
#pragma unroll
    for (int p = 0; p < 2; p++)
#pragma unroll
        for (int bb = 0; bb < 4; bb++) acc[p][bb] = 0ull;

    u64t bufA[8], bufB[8];
#pragma unroll
    for (int j = 0; j < 4; j++)
        ldcg2(lane_src + j * BB, bufA[j * 2 + 0], bufA[j * 2 + 1]);

#pragma unroll
    for (int c = 0; c < 8; c++) {
        u64t* cur = (c & 1) ? bufB : bufA;
        u64t* nxt = (c & 1) ? bufA : bufB;
        if (c < 7) {
            const float* hp2 = lane_src + (size_t)(c + 1) * 4 * BB;
#pragma unroll
            for (int j = 0; j < 4; j++)
                ldcg2(hp2 + j * BB, nxt[j * 2 + 0], nxt[j * 2 + 1]);
        }
#pragma unroll
        for (int j = 0; j < 4; j++) {
            const int kk = c * 4 + j;
            ulonglong2 wv = *(const ulonglong2*)(wrow + kk * 16);
            float2 hA = unpack2(cur[j * 2 + 0]);
            float2 hB = unpack2(cur[j * 2 + 1]);
            u64t hs0 = pack2(hA.x, hA.x);
            u64t hs1 = pack2(hA.y, hA.y);
            u64t hs2 = pack2(hB.x, hB.x);
            u64t hs3 = pack2(hB.y, hB.y);
            acc[0][0] = ffma2(hs0, wv.x, acc[0][0]);
            acc[1][0] = ffma2(hs0, wv.y, acc[1][0]);
            acc[0][1] = ffma2(hs1, wv.x, acc[0][1]);
            acc[1][1] = ffma2(hs1, wv.y, acc[1][1]);
            acc[0][2] = ffma2(hs2, wv.x, acc[0][2]);
            acc[1][2] = ffma2(hs2, wv.y, acc[1][2]);
            acc[0][3] = ffma2(hs3, wv.x, acc[0][3]);
            acc[1][3] = ffma2(hs3, wv.y, acc[1][3]);
        }
    }
#pragma unroll
    for (int p = 0; p < 2; p++) {
        const int gc0 = gco * 4 + p * 2;
#pragma unroll
        for (int bb = 0; bb < 4; bb++) {
            float2 v = unpack2(acc[p][bb]);
            ps[gc0 * 32 + bq * 4 + bb]       = v.x;
            ps[(gc0 + 1) * 32 + bq * 4 + bb] = v.y;
        }
    }
}

// ---------------- Kernel 1: fused persistent LSTM ----------------
// 128 CTAs x 512 threads. CTA owns 4 h-cols jc -> 16 gate-cols. Per step:
//   h-GEMM (step t, from hT) + x-GEMM (step t+1, from xT) -> SMEM partials,
//   gates (A: reduce ps + psx + bias, B: c/h update), grid barrier.
// x_pre never touches gmem: psx ping-pong buffers in SMEM.
//
// SMEM layout (floats):
#define SH_W    0                      // Wh [k][gc]           512*16 = 8192
#define SH_WI   (SH_W   + 8192)        // Wi [k][gc]           8192
#define SH_PS   (SH_WI  + 8192)        // h partials [w][gc][b] 8192
#define SH_PSX  (SH_PS  + 8192)        // x partials x2 bufs   16384
#define SH_BIAS (SH_PSX + 16384)       // bias [gc]            16
#define SH_C    (SH_BIAS + 16)         // cell [jj][b]         128
#define SH_G    (SH_C   + 128)         // gates [gc][b]        512
#define SH_HO   (SH_G   + 512)         // h out [b][jj]        128
#define SH_TOTAL_FLOATS (SH_HO + 128)

extern __shared__ float smem_p[];

__global__ __launch_bounds__(512, 1) void lstm_fused_kernel(
    const float* __restrict__ Whi, const float* __restrict__ Whf,
    const float* __restrict__ Who, const float* __restrict__ Whg,
    const float* __restrict__ Wii, const float* __restrict__ Wif,
    const float* __restrict__ Wio, const float* __restrict__ Wig,
    const float* __restrict__ bi, const float* __restrict__ bf,
    const float* __restrict__ bo, const float* __restrict__ bg,
    const float* __restrict__ c0,
    float* __restrict__ out,
    int write_tail)
{
    float* sh_w   = smem_p + SH_W;
    float* sh_wi  = smem_p + SH_WI;
    float* sh_ps  = smem_p + SH_PS;
    float* sh_psx = smem_p + SH_PSX;
    float* sh_bias= smem_p + SH_BIAS;
    float* sh_c   = smem_p + SH_C;
    float* sh_g   = smem_p + SH_G;
    float* sh_ho  = smem_p + SH_HO;

    const int tid  = threadIdx.x;
    const int lane = tid & 31;
    const int w    = tid >> 5;              // 0..15
    const int jc   = blockIdx.x * 4;        // h-column base

    const int bq  = lane & 7;               // 0..7 -> 4 batches
    const int gco = lane >> 3;               // 0..3 -> 4 gate-cols

    // ---- one-time: weight slices [k][gc], gc = q*4 + jj ----
    for (int e = tid; e < 512 * 16; e += 512) {
        int k   = e >> 4;
        int gcl = e & 15;
        int q   = gcl >> 2;
        int jj  = gcl & 3;
        const float* Wh = (q == 0) ? Whi : (q == 1) ? Whf : (q == 2) ? Who : Whg;
        const float* Wi = (q == 0) ? Wii : (q == 1) ? Wif : (q == 2) ? Wio : Wig;
        sh_w[e]  = Wh[(size_t)k * HH + jc + jj];
        sh_wi[e] = Wi[(size_t)k * HH + jc + jj];
    }
    if (tid < 16) {
        int q  = tid >> 2;
        int jj = tid & 3;
        const float* bias = (q == 0) ? bi : (q == 1) ? bf : (q == 2) ? bo : bg;
        sh_bias[tid] = bias[jc + jj];
    }
    if (tid < 128) {
        int jj = tid >> 5;
        int b  = tid & 31;
        sh_c[jj * 32 + b] = c0[b * HH + jc + jj];
    }
    __syncthreads();

    const int kb = w * 32;                   // warp k-slice base

    // gates phase A mapping
    const int a_gc = tid >> 5;               // 0..15 (warp-uniform activation)
    const int a_b  = tid & 31;
    const int a_q  = a_gc >> 2;
    // gates phase B mapping (tid<128)
    const int g_jj = tid >> 5;
    const int g_b  = tid & 31;

    const int lane_off = kb * 32 + bq * 4;
    const int wrow_off = kb * 16 + gco * 4;

    unsigned* bar_count = &g_bar_count;
    unsigned* bar_phase = &g_bar_phase;

    // ---- prologue: x-GEMM for t=0 into psx buffer 0 ----
    gemm_slice(g_xT + lane_off, sh_wi + wrow_off, sh_psx + 0 * 8192 + w * 512, gco, bq);

    for (int t = 0; t < TT; ++t) {
        const float* hT_r = g_hT[t & 1];
        float*       hT_w = g_hT[(t + 1) & 1];

        // ---- h-GEMM (step t) ----
        gemm_slice(hT_r + lane_off, sh_w + wrow_off, sh_ps + w * 512, gco, bq);

        // ---- x-GEMM (step t+1) into ping-pong buffer ----
        if (t + 1 < TT)
            gemm_slice(g_xT + (size_t)(t + 1) * (512 * 32) + lane_off,
                       sh_wi + wrow_off,
                       sh_psx + ((t + 1) & 1) * 8192 + w * 512, gco, bq);
        __syncthreads();

        // ---- gates phase A (ALL 512 threads): reduce + activation ----
        {
            const int off = a_gc * 32 + a_b;
            float s = sh_bias[a_gc];
            const float* px = sh_psx + (t & 1) * 8192;
#pragma unroll
            for (int ws16 = 0; ws16 < 16; ws16++)
                s += sh_ps[ws16 * 512 + off];
#pragma unroll
            for (int ws16 = 0; ws16 < 16; ws16++)
                s += px[ws16 * 512 + off];
            float g;
            if (a_q == 3)      g = tanhf(s);
            else               g = __fdividef(1.0f, 1.0f + __expf(-s));
            sh_g[off] = g;
        }
        __syncthreads();

        // ---- gates phase B (128 threads): c/h update ----
        if (tid < 128) {
            const int jj = g_jj, b = g_b;
            float it = sh_g[(0 * 4 + jj) * 32 + b];
            float ft = sh_g[(1 * 4 + jj) * 32 + b];
            float ot = sh_g[(2 * 4 + jj) * 32 + b];
            float gt = sh_g[(3 * 4 + jj) * 32 + b];
            float cn = ft * sh_c[jj * 32 + b] + it * gt;
            float hn = ot * tanhf(cn);
            sh_c[jj * 32 + b] = cn;
            sh_ho[b * 4 + jj] = hn;
            hT_w[(jc + jj) * BB + b] = hn;     // coalesced 128B per jj
        }
        __syncthreads();

        // ---- barrier: release arrival; releaser skips its poll ----
        bool releaser = false;
        if (tid == 0) {
            unsigned a;
            asm volatile("atom.release.gpu.global.add.u32 %0, [%1], %2;"
                         : "=r"(a) : "l"(bar_count), "r"(1u) : "memory");
            if (a == (unsigned)(GRID_P - 1)) {
                releaser = true;
                *bar_count = 0;
                asm volatile("st.release.gpu.global.u32 [%0], %1;"
                             :: "l"(bar_phase), "r"((unsigned)(t + 1)) : "memory");
            }
        }
        if (tid < 32) {
            int b = tid;
            *(float4*)(out + ((size_t)b * TT + t) * HH + jc) = *(float4*)(sh_ho + b * 4);
        }
        if (tid == 0 && !releaser) {
            unsigned ph;
            for (;;) {
                asm volatile("ld.acquire.gpu.global.u32 %0, [%1];"
                             : "=r"(ph) : "l"(bar_phase) : "memory");
                if ((int)ph > t) break;
                __nanosleep(32);
            }
        }
        __syncthreads();
    }

    // ---- final (h_t, c_t) tail ----
    if (write_tail && tid < 128) {
        int jj = tid >> 5;
        int b  = tid & 31;
        const size_t tail = (size_t)BB * TT * HH;
        out[tail + (size_t)b * HH + jc + jj]                   = sh_ho[b * 4 + jj];
        out[tail + (size_t)BB * HH + (size_t)b * HH + jc + jj] = sh_c[jj * 32 + b];
    }
}

// ---------------- launch ----------------
extern "C" void kernel_launch(void* const* d_in, const int* in_sizes, int n_in,
                              void* d_out, int out_size) {
    const float* x   = (const float*)d_in[0];
    const float* h0  = (const float*)d_in[1];
    const float* c0  = (const float*)d_in[2];
    const float* Wii = (const float*)d_in[3];
    const float* Wif = (const float*)d_in[4];
    const float* Wio = (const float*)d_in[5];
    const float* Wig = (const float*)d_in[6];
    const float* Whi = (const float*)d_in[7];
    const float* Whf = (const float*)d_in[8];
    const float* Who = (const float*)d_in[9];
    const float* Whg = (const float*)d_in[10];
    const float* bi  = (const float*)d_in[11];
    const float* bf_ = (const float*)d_in[12];
    const float* bo  = (const float*)d_in[13];
    const float* bg  = (const float*)d_in[14];
    float* out = (float*)d_out;

    const size_t prep_smem = (size_t)32 * XPAD * sizeof(float);
    const size_t smem_bytes = SH_TOTAL_FLOATS * sizeof(float);
    cudaFuncSetAttribute(prep_kernel,
                         cudaFuncAttributeMaxDynamicSharedMemorySize,
                         (int)prep_smem);
    cudaFuncSetAttribute(lstm_fused_kernel,
                         cudaFuncAttributeMaxDynamicSharedMemorySize,
                         (int)smem_bytes);

    const long long tail = (long long)BB * TT * HH;
    const int write_tail = ((long long)out_size >= tail + 2LL * BB * HH) ? 1 : 0;

    prep_kernel<<<TT, 512, prep_smem>>>(x, h0);
    lstm_fused_kernel<<<GRID_P, 512, smem_bytes>>>(
        Whi, Whf, Who, Whg, Wii, Wif, Wio, Wig,
        bi, bf_, bo, bg, c0, out, write_tail);
}

// round 15
// speedup vs baseline: 1.3151x; 1.3151x over previous
#include <cuda_runtime.h>
#include <math.h>

#define BB 32
#define TT 1024
#define II 512
#define HH 512
#define G4 2048      // 4*H
#define GRID_P 128   // persistent CTAs (<=148 -> co-resident, deadlock-free)

typedef unsigned long long u64t;

// ---- packed fp32x2 helpers (Blackwell FFMA2) ----
__device__ __forceinline__ u64t ffma2(u64t a, u64t b, u64t c) {
    u64t d;
    asm("fma.rn.f32x2 %0, %1, %2, %3;" : "=l"(d) : "l"(a), "l"(b), "l"(c));
    return d;
}
__device__ __forceinline__ u64t pack2(float x, float y) {
    u64t d;
    asm("mov.b64 %0, {%1, %2};" : "=l"(d) : "f"(x), "f"(y));
    return d;
}
__device__ __forceinline__ float2 unpack2(u64t v) {
    float2 r;
    asm("mov.b64 {%0, %1}, %2;" : "=f"(r.x), "=f"(r.y) : "l"(v));
    return r;
}
// L2-coherent 16B load (L1 is stale across CTAs; REQUIRED for h double-buffer)
__device__ __forceinline__ void ldcg2(const float* p, u64t& a, u64t& b) {
    asm volatile("ld.global.cg.v2.u64 {%0,%1}, [%2];" : "=l"(a), "=l"(b) : "l"(p));
}

// ---------------- scratch (static device globals; no allocation) ----------------
__device__ float    g_xT[(size_t)TT * II * BB];     // x transposed [t][k][b]  64 MB
__device__ float    g_hT[2][HH * BB];               // double-buffered h^T [k][b]
__device__ unsigned g_bar_count;
__device__ unsigned g_bar_phase;

// ---------------- Kernel 0: transpose x -> xT[t][k][b]; init hT/barrier ---------
#define XPAD 520
__global__ __launch_bounds__(512) void prep_kernel(
    const float* __restrict__ x, const float* __restrict__ h0)
{
    extern __shared__ float xs[];          // [32][XPAD]
    const int t   = blockIdx.x;
    const int tid = threadIdx.x;

#pragma unroll
    for (int i = 0; i < 8; i++) {
        int idx = tid + i * 512;
        int b   = idx >> 7;
        int kc  = idx & 127;
        float4 v = *(const float4*)(x + ((size_t)b * TT + t) * 512 + kc * 4);
        *(float4*)&xs[b * XPAD + kc * 4] = v;
    }
    __syncthreads();

    float* dst = g_xT + (size_t)t * (512 * 32);
#pragma unroll
    for (int i = 0; i < 8; i++) {
        int idx = tid + i * 512;
        int k   = idx >> 3;
        int bq  = idx & 7;
        float4 v;
        v.x = xs[(bq * 4 + 0) * XPAD + k];
        v.y = xs[(bq * 4 + 1) * XPAD + k];
        v.z = xs[(bq * 4 + 2) * XPAD + k];
        v.w = xs[(bq * 4 + 3) * XPAD + k];
        *(float4*)(dst + k * 32 + bq * 4) = v;
    }

    if (t == 0) {
        for (int i = tid; i < BB * HH; i += 512) {
            int b = i >> 9;
            int j = i & 511;
            g_hT[0][j * BB + b] = h0[i];
        }
        if (tid == 0) { g_bar_count = 0; g_bar_phase = 0; }
    }
}

// ---------------- 64-k GEMM slice (round-10 inner loop, 16 chunks) ---------------
__device__ __forceinline__ void gemm_slice64(
    const float* __restrict__ src, const float* __restrict__ wrow,
    float* __restrict__ ps, const int gco, const int bq)
{
    u64t acc[2][4];
#pragma unroll
    for (int p = 0; p < 2; p++)
#pragma unroll
        for (int bb = 0; bb < 4; bb++) acc[p][bb] = 0ull;

    u64t bufA[8], bufB[8];
#pragma unroll
    for (int j = 0; j < 4; j++)
        ldcg2(src + j * BB, bufA[j * 2 + 0], bufA[j * 2 + 1]);

#pragma unroll
    for (int c = 0; c < 16; c++) {
        u64t* cur = (c & 1) ? bufB : bufA;
        u64t* nxt = (c & 1) ? bufA : bufB;
        if (c < 15) {
            const float* hp2 = src + (size_t)(c + 1) * 4 * BB;
#pragma unroll
            for (int j = 0; j < 4; j++)
                ldcg2(hp2 + j * BB, nxt[j * 2 + 0], nxt[j * 2 + 1]);
        }
#pragma unroll
        for (int j = 0; j < 4; j++) {
            const int kk = c * 4 + j;
            ulonglong2 wv = *(const ulonglong2*)(wrow + kk * 16);
            float2 hA = unpack2(cur[j * 2 + 0]);
            float2 hB = unpack2(cur[j * 2 + 1]);
            u64t hs0 = pack2(hA.x, hA.x);
            u64t hs1 = pack2(hA.y, hA.y);
            u64t hs2 = pack2(hB.x, hB.x);
            u64t hs3 = pack2(hB.y, hB.y);
            acc[0][0] = ffma2(hs0, wv.x, acc[0][0]);
            acc[1][0] = ffma2(hs0, wv.y, acc[1][0]);
            acc[0][1] = ffma2(hs1, wv.x, acc[0][1]);
            acc[1][1] = ffma2(hs1, wv.y, acc[1][1]);
            acc[0][2] = ffma2(hs2, wv.x, acc[0][2]);
            acc[1][2] = ffma2(hs2, wv.y, acc[1][2]);
            acc[0][3] = ffma2(hs3, wv.x, acc[0][3]);
            acc[1][3] = ffma2(hs3, wv.y, acc[1][3]);
        }
    }
#pragma unroll
    for (int p = 0; p < 2; p++) {
        const int gc0 = gco * 4 + p * 2;
#pragma unroll
        for (int bb = 0; bb < 4; bb++) {
            float2 v = unpack2(acc[p][bb]);
            ps[gc0 * 32 + bq * 4 + bb]       = v.x;
            ps[(gc0 + 1) * 32 + bq * 4 + bb] = v.y;
        }
    }
}

// ---------------- Kernel 1: warp-specialized fused persistent LSTM ----------------
// Warps 0-7 (h-group): h-GEMM(t) + gates + hT write + grid barrier (critical path).
// Warps 8-15 (x-group): x-GEMM(tx) from xT into a 4-deep psx ring, up to 4 steps
// ahead. Coupling via volatile SMEM counters + named barriers (no __syncthreads
// after the split).
//
// SMEM layout (floats):
#define SH_W    0                      // Wh [k][gc]            8192
#define SH_WI   (SH_W   + 8192)        // Wi [k][gc]            8192
#define SH_PS   (SH_WI  + 8192)        // h partials [8w][gc][b] 4096
#define SH_PSX  (SH_PS  + 4096)        // x partials ring 4x[8w][gc][b] 16384
#define SH_BIAS (SH_PSX + 16384)       // bias [gc]             16
#define SH_C    (SH_BIAS + 16)         // cell [jj][b]          128
#define SH_G    (SH_C   + 128)         // gates [gc][b]         512
#define SH_HO   (SH_G   + 512)         // h out [b][jj]         128
#define SH_FLG  (SH_HO  + 128)         // produced/consumed     8
#define SH_TOTAL_FLOATS (SH_FLG + 8)

extern __shared__ float smem_p[];

__global__ __launch_bounds__(512, 1) void lstm_fused_kernel(
    const float* __restrict__ Whi, const float* __restrict__ Whf,
    const float* __restrict__ Who, const float* __restrict__ Whg,
    const float* __restrict__ Wii, const float* __restrict__ Wif,
    const float* __restrict__ Wio, const float* __restrict__ Wig,
    const float* __restrict__ bi, const float* __restrict__ bf,
    const float* __restrict__ bo, const float* __restrict__ bg,
    const float* __restrict__ c0,
    float* __restrict__ out,
    int write_tail)
{
    float* sh_w   = smem_p + SH_W;
    float* sh_wi  = smem_p + SH_WI;
    float* sh_ps  = smem_p + SH_PS;
    float* sh_psx = smem_p + SH_PSX;
    float* sh_bias= smem_p + SH_BIAS;
    float* sh_c   = smem_p + SH_C;
    float* sh_g   = smem_p + SH_G;
    float* sh_ho  = smem_p + SH_HO;
    volatile int* produced = (volatile int*)(smem_p + SH_FLG);
    volatile int* consumed = (volatile int*)(smem_p + SH_FLG) + 1;

    const int tid  = threadIdx.x;
    const int lane = tid & 31;
    const int w    = tid >> 5;              // 0..15
    const int jc   = blockIdx.x * 4;        // h-column base

    const int bq  = lane & 7;               // 0..7 -> 4 batches
    const int gco = lane >> 3;               // 0..3 -> 4 gate-cols

    // ---- one-time: weight slices [k][gc], gc = q*4 + jj (all 512 threads) ----
    for (int e = tid; e < 512 * 16; e += 512) {
        int k   = e >> 4;
        int gcl = e & 15;
        int q   = gcl >> 2;
        int jj  = gcl & 3;
        const float* Wh = (q == 0) ? Whi : (q == 1) ? Whf : (q == 2) ? Who : Whg;
        const float* Wi = (q == 0) ? Wii : (q == 1) ? Wif : (q == 2) ? Wio : Wig;
        sh_w[e]  = Wh[(size_t)k * HH + jc + jj];
        sh_wi[e] = Wi[(size_t)k * HH + jc + jj];
    }
    if (tid < 16) {
        int q  = tid >> 2;
        int jj = tid & 3;
        const float* bias = (q == 0) ? bi : (q == 1) ? bf : (q == 2) ? bo : bg;
        sh_bias[tid] = bias[jc + jj];
    }
    if (tid < 128) {
        int jj = tid >> 5;
        int b  = tid & 31;
        sh_c[jj * 32 + b] = c0[b * HH + jc + jj];
    }
    if (tid == 0) { *produced = 0; *consumed = 0; }
    __syncthreads();   // last full-block sync

    unsigned* bar_count = &g_bar_count;
    unsigned* bar_phase = &g_bar_phase;

    if (w >= 8) {
        // ================= x-producer group (warps 8-15) =================
        const int wx  = w - 8;
        const int kb  = wx * 64;
        const float* wrow = sh_wi + kb * 16 + gco * 4;
        const int lane_off = kb * 32 + bq * 4;

        for (int tx = 0; tx < TT; ++tx) {
            // ring backpressure: stay <= 4 ahead of consumption
            while (*consumed < tx - 3) __nanosleep(64);
            gemm_slice64(g_xT + (size_t)tx * (512 * 32) + lane_off, wrow,
                         sh_psx + (tx & 3) * 4096 + wx * 512, gco, bq);
            asm volatile("bar.sync 2, 256;" ::: "memory");
            if (tid == 256) { __threadfence_block(); *produced = tx + 1; }
        }
    } else {
        // ================= h-consumer group (warps 0-7) =================
        const int kb = w * 64;
        const float* wrow = sh_w + kb * 16 + gco * 4;
        const int lane_off = kb * 32 + bq * 4;

        const int g_jj = tid >> 5;           // phase B mapping (tid<128)
        const int g_b  = tid & 31;

        for (int t = 0; t < TT; ++t) {
            const float* hT_r = g_hT[t & 1];
            float*       hT_w = g_hT[(t + 1) & 1];

            // ---- h-GEMM (step t) ----
            gemm_slice64(hT_r + lane_off, wrow, sh_ps + w * 512, gco, bq);
            asm volatile("bar.sync 1, 256;" ::: "memory");

            // ---- wait for x partials of step t ----
            while (*produced < t + 1) __nanosleep(32);
            __threadfence_block();

            // ---- gates phase A (256 threads, 2 items each) ----
            {
                const float* px = sh_psx + (t & 3) * 4096;
#pragma unroll
                for (int it = 0; it < 2; it++) {
                    const int item = tid + it * 256;
                    const int gc = item >> 5;
                    const int b  = item & 31;
                    const int off = gc * 32 + b;
                    float s = sh_bias[gc];
#pragma unroll
                    for (int s8 = 0; s8 < 8; s8++)
                        s += sh_ps[s8 * 512 + off];
#pragma unroll
                    for (int s8 = 0; s8 < 8; s8++)
                        s += px[s8 * 512 + off];
                    float g;
                    if ((gc >> 2) == 3) g = tanhf(s);
                    else                g = __fdividef(1.0f, 1.0f + __expf(-s));
                    sh_g[off] = g;
                }
            }
            asm volatile("bar.sync 1, 256;" ::: "memory");
            if (tid == 0) { __threadfence_block(); *consumed = t + 1; }

            // ---- gates phase B (128 threads): c/h update ----
            if (tid < 128) {
                const int jj = g_jj, b = g_b;
                float it = sh_g[(0 * 4 + jj) * 32 + b];
                float ft = sh_g[(1 * 4 + jj) * 32 + b];
                float ot = sh_g[(2 * 4 + jj) * 32 + b];
                float gt = sh_g[(3 * 4 + jj) * 32 + b];
                float cn = ft * sh_c[jj * 32 + b] + it * gt;
                float hn = ot * tanhf(cn);
                sh_c[jj * 32 + b] = cn;
                sh_ho[b * 4 + jj] = hn;
                hT_w[(jc + jj) * BB + b] = hn;     // coalesced 128B per jj
            }
            asm volatile("bar.sync 1, 256;" ::: "memory");

            // ---- grid barrier: release arrival; releaser skips its poll ----
            bool releaser = false;
            if (tid == 0) {
                unsigned a;
                asm volatile("atom.release.gpu.global.add.u32 %0, [%1], %2;"
                             : "=r"(a) : "l"(bar_count), "r"(1u) : "memory");
                if (a == (unsigned)(GRID_P - 1)) {
                    releaser = true;
                    *bar_count = 0;
                    asm volatile("st.release.gpu.global.u32 [%0], %1;"
                                 :: "l"(bar_phase), "r"((unsigned)(t + 1)) : "memory");
                }
            }
            if (tid < 32) {
                int b = tid;
                *(float4*)(out + ((size_t)b * TT + t) * HH + jc) = *(float4*)(sh_ho + b * 4);
            }
            if (tid == 0 && !releaser) {
                unsigned ph;
                for (;;) {
                    asm volatile("ld.acquire.gpu.global.u32 %0, [%1];"
                                 : "=r"(ph) : "l"(bar_phase) : "memory");
                    if ((int)ph > t) break;
                    __nanosleep(32);
                }
            }
            asm volatile("bar.sync 1, 256;" ::: "memory");
        }

        // ---- final (h_t, c_t) tail ----
        if (write_tail && tid < 128) {
            const int jj = g_jj, b = g_b;
            const size_t tail = (size_t)BB * TT * HH;
            out[tail + (size_t)b * HH + jc + jj]                   = sh_ho[b * 4 + jj];
            out[tail + (size_t)BB * HH + (size_t)b * HH + jc + jj] = sh_c[jj * 32 + b];
        }
    }
}

// ---------------- launch ----------------
extern "C" void kernel_launch(void* const* d_in, const int* in_sizes, int n_in,
                              void* d_out, int out_size) {
    const float* x   = (const float*)d_in[0];
    const float* h0  = (const float*)d_in[1];
    const float* c0  = (const float*)d_in[2];
    const float* Wii = (const float*)d_in[3];
    const float* Wif = (const float*)d_in[4];
    const float* Wio = (const float*)d_in[5];
    const float* Wig = (const float*)d_in[6];
    const float* Whi = (const float*)d_in[7];
    const float* Whf = (const float*)d_in[8];
    const float* Who = (const float*)d_in[9];
    const float* Whg = (const float*)d_in[10];
    const float* bi  = (const float*)d_in[11];
    const float* bf_ = (const float*)d_in[12];
    const float* bo  = (const float*)d_in[13];
    const float* bg  = (const float*)d_in[14];
    float* out = (float*)d_out;

    const size_t prep_smem = (size_t)32 * XPAD * sizeof(float);
    const size_t smem_bytes = SH_TOTAL_FLOATS * sizeof(float);
    cudaFuncSetAttribute(prep_kernel,
                         cudaFuncAttributeMaxDynamicSharedMemorySize,
                         (int)prep_smem);
    cudaFuncSetAttribute(lstm_fused_kernel,
                         cudaFuncAttributeMaxDynamicSharedMemorySize,
                         (int)smem_bytes);

    const long long tail = (long long)BB * TT * HH;
    const int write_tail = ((long long)out_size >= tail + 2LL * BB * HH) ? 1 : 0;

    prep_kernel<<<TT, 512, prep_smem>>>(x, h0);
    lstm_fused_kernel<<<GRID_P, 512, smem_bytes>>>(
        Whi, Whf, Who, Whg, Wii, Wif, Wio, Wig,
        bi, bf_, bo, bg, c0, out, write_tail);
}

// round 16
// speedup vs baseline: 1.3401x; 1.0190x over previous
#include <cuda_runtime.h>
#include <math.h>

#define BB 32
#define TT 1024
#define II 512
#define HH 512
#define G4 2048      // 4*H
#define GRID_P 128   // persistent CTAs (<=148 -> co-resident, deadlock-free)

typedef unsigned long long u64t;

// ---- packed fp32x2 helpers (Blackwell FFMA2) ----
__device__ __forceinline__ u64t ffma2(u64t a, u64t b, u64t c) {
    u64t d;
    asm("fma.rn.f32x2 %0, %1, %2, %3;" : "=l"(d) : "l"(a), "l"(b), "l"(c));
    return d;
}
__device__ __forceinline__ u64t pack2(float x, float y) {
    u64t d;
    asm("mov.b64 %0, {%1, %2};" : "=l"(d) : "f"(x), "f"(y));
    return d;
}
__device__ __forceinline__ float2 unpack2(u64t v) {
    float2 r;
    asm("mov.b64 {%0, %1}, %2;" : "=f"(r.x), "=f"(r.y) : "l"(v));
    return r;
}
// L2-coherent 16B load (L1 is stale across CTAs; REQUIRED for h double-buffer)
__device__ __forceinline__ void ldcg2(const float* p, u64t& a, u64t& b) {
    asm volatile("ld.global.cg.v2.u64 {%0,%1}, [%2];" : "=l"(a), "=l"(b) : "l"(p));
}

// ---------------- scratch (static device globals; no allocation) ----------------
__device__ float    g_xT[(size_t)TT * II * BB];     // x transposed [t][k][b]  64 MB
__device__ float    g_hT[2][HH * BB];               // double-buffered h^T [k][b]
__device__ unsigned g_bar_count;
__device__ unsigned g_bar_phase;

// ---------------- Kernel 0: transpose x -> xT[t][k][b]; init hT/barrier ---------
#define XPAD 520
__global__ __launch_bounds__(512) void prep_kernel(
    const float* __restrict__ x, const float* __restrict__ h0)
{
    extern __shared__ float xs[];          // [32][XPAD]
    const int t   = blockIdx.x;
    const int tid = threadIdx.x;

#pragma unroll
    for (int i = 0; i < 8; i++) {
        int idx = tid + i * 512;
        int b   = idx >> 7;
        int kc  = idx & 127;
        float4 v = *(const float4*)(x + ((size_t)b * TT + t) * 512 + kc * 4);
        *(float4*)&xs[b * XPAD + kc * 4] = v;
    }
    __syncthreads();

    float* dst = g_xT + (size_t)t * (512 * 32);
#pragma unroll
    for (int i = 0; i < 8; i++) {
        int idx = tid + i * 512;
        int k   = idx >> 3;
        int bq  = idx & 7;
        float4 v;
        v.x = xs[(bq * 4 + 0) * XPAD + k];
        v.y = xs[(bq * 4 + 1) * XPAD + k];
        v.z = xs[(bq * 4 + 2) * XPAD + k];
        v.w = xs[(bq * 4 + 3) * XPAD + k];
        *(float4*)(dst + k * 32 + bq * 4) = v;
    }

    if (t == 0) {
        for (int i = tid; i < BB * HH; i += 512) {
            int b = i >> 9;
            int j = i & 511;
            g_hT[0][j * BB + b] = h0[i];
        }
        if (tid == 0) { g_bar_count = 0; g_bar_phase = 0; }
    }
}

// ---------------- 64-k GEMM slice (round-10 inner loop, 16 chunks) ---------------
__device__ __forceinline__ void gemm_slice64(
    const float* __restrict__ src, const float* __restrict__ wrow,
    float* __restrict__ ps, const int gco, const int bq)
{
    u64t acc[2][4];
#pragma unroll
    for (int p = 0; p < 2; p++)
#pragma unroll
        for (int bb = 0; bb < 4; bb++) acc[p][bb] = 0ull;

    u64t bufA[8], bufB[8];
#pragma unroll
    for (int j = 0; j < 4; j++)
        ldcg2(src + j * BB, bufA[j * 2 + 0], bufA[j * 2 + 1]);

#pragma unroll
    for (int c = 0; c < 16; c++) {
        u64t* cur = (c & 1) ? bufB : bufA;
        u64t* nxt = (c & 1) ? bufA : bufB;
        if (c < 15) {
            const float* hp2 = src + (size_t)(c + 1) * 4 * BB;
#pragma unroll
            for (int j = 0; j < 4; j++)
                ldcg2(hp2 + j * BB, nxt[j * 2 + 0], nxt[j * 2 + 1]);
        }
#pragma unroll
        for (int j = 0; j < 4; j++) {
            const int kk = c * 4 + j;
            ulonglong2 wv = *(const ulonglong2*)(wrow + kk * 16);
            float2 hA = unpack2(cur[j * 2 + 0]);
            float2 hB = unpack2(cur[j * 2 + 1]);
            u64t hs0 = pack2(hA.x, hA.x);
            u64t hs1 = pack2(hA.y, hA.y);
            u64t hs2 = pack2(hB.x, hB.x);
            u64t hs3 = pack2(hB.y, hB.y);
            acc[0][0] = ffma2(hs0, wv.x, acc[0][0]);
            acc[1][0] = ffma2(hs0, wv.y, acc[1][0]);
            acc[0][1] = ffma2(hs1, wv.x, acc[0][1]);
            acc[1][1] = ffma2(hs1, wv.y, acc[1][1]);
            acc[0][2] = ffma2(hs2, wv.x, acc[0][2]);
            acc[1][2] = ffma2(hs2, wv.y, acc[1][2]);
            acc[0][3] = ffma2(hs3, wv.x, acc[0][3]);
            acc[1][3] = ffma2(hs3, wv.y, acc[1][3]);
        }
    }
#pragma unroll
    for (int p = 0; p < 2; p++) {
        const int gc0 = gco * 4 + p * 2;
#pragma unroll
        for (int bb = 0; bb < 4; bb++) {
            float2 v = unpack2(acc[p][bb]);
            ps[gc0 * 32 + bq * 4 + bb]       = v.x;
            ps[(gc0 + 1) * 32 + bq * 4 + bb] = v.y;
        }
    }
}

// ---------------- Kernel 1: warp-specialized fused persistent LSTM ----------------
// ARBITER-AWARE MAPPING (hi-wid-first scheduler):
//   Warps 8-15 (HIGH priority) = h-consumer group: h-GEMM(t) + gates + hT write
//     + grid barrier — the recurrence-critical chain.
//   Warps 0-7  (LOW priority)  = x-producer group: x-GEMM ring (4 deep), absorbs
//     stall slots only.
//
// SMEM layout (floats):
#define SH_W    0                      // Wh [k][gc]            8192
#define SH_WI   (SH_W   + 8192)        // Wi [k][gc]            8192
#define SH_PS   (SH_WI  + 8192)        // h partials [8w][gc][b] 4096
#define SH_PSX  (SH_PS  + 4096)        // x partials ring 4x[8w][gc][b] 16384
#define SH_BIAS (SH_PSX + 16384)       // bias [gc]             16
#define SH_C    (SH_BIAS + 16)         // cell [jj][b]          128
#define SH_G    (SH_C   + 128)         // gates [gc][b]         512
#define SH_HO   (SH_G   + 512)         // h out [b][jj]         128
#define SH_FLG  (SH_HO  + 128)         // produced/consumed     8
#define SH_TOTAL_FLOATS (SH_FLG + 8)

extern __shared__ float smem_p[];

__global__ __launch_bounds__(512, 1) void lstm_fused_kernel(
    const float* __restrict__ Whi, const float* __restrict__ Whf,
    const float* __restrict__ Who, const float* __restrict__ Whg,
    const float* __restrict__ Wii, const float* __restrict__ Wif,
    const float* __restrict__ Wio, const float* __restrict__ Wig,
    const float* __restrict__ bi, const float* __restrict__ bf,
    const float* __restrict__ bo, const float* __restrict__ bg,
    const float* __restrict__ c0,
    float* __restrict__ out,
    int write_tail)
{
    float* sh_w   = smem_p + SH_W;
    float* sh_wi  = smem_p + SH_WI;
    float* sh_ps  = smem_p + SH_PS;
    float* sh_psx = smem_p + SH_PSX;
    float* sh_bias= smem_p + SH_BIAS;
    float* sh_c   = smem_p + SH_C;
    float* sh_g   = smem_p + SH_G;
    float* sh_ho  = smem_p + SH_HO;
    volatile int* produced = (volatile int*)(smem_p + SH_FLG);
    volatile int* consumed = (volatile int*)(smem_p + SH_FLG) + 1;

    const int tid  = threadIdx.x;
    const int lane = tid & 31;
    const int w    = tid >> 5;              // 0..15
    const int jc   = blockIdx.x * 4;        // h-column base

    const int bq  = lane & 7;               // 0..7 -> 4 batches
    const int gco = lane >> 3;               // 0..3 -> 4 gate-cols

    // ---- one-time: weight slices [k][gc], gc = q*4 + jj (all 512 threads) ----
    for (int e = tid; e < 512 * 16; e += 512) {
        int k   = e >> 4;
        int gcl = e & 15;
        int q   = gcl >> 2;
        int jj  = gcl & 3;
        const float* Wh = (q == 0) ? Whi : (q == 1) ? Whf : (q == 2) ? Who : Whg;
        const float* Wi = (q == 0) ? Wii : (q == 1) ? Wif : (q == 2) ? Wio : Wig;
        sh_w[e]  = Wh[(size_t)k * HH + jc + jj];
        sh_wi[e] = Wi[(size_t)k * HH + jc + jj];
    }
    if (tid < 16) {
        int q  = tid >> 2;
        int jj = tid & 3;
        const float* bias = (q == 0) ? bi : (q == 1) ? bf : (q == 2) ? bo : bg;
        sh_bias[tid] = bias[jc + jj];
    }
    if (tid < 128) {
        int jj = tid >> 5;
        int b  = tid & 31;
        sh_c[jj * 32 + b] = c0[b * HH + jc + jj];
    }
    if (tid == 0) { *produced = 0; *consumed = 0; }
    __syncthreads();   // last full-block sync

    unsigned* bar_count = &g_bar_count;
    unsigned* bar_phase = &g_bar_phase;

    if (w < 8) {
        // ============ x-producer group (warps 0-7, LOW arbiter priority) ============
        const int wx  = w;
        const int kb  = wx * 64;
        const float* wrow = sh_wi + kb * 16 + gco * 4;
        const int lane_off = kb * 32 + bq * 4;

        for (int tx = 0; tx < TT; ++tx) {
            // ring backpressure: stay <= 4 ahead of consumption
            while (*consumed < tx - 3) __nanosleep(64);
            gemm_slice64(g_xT + (size_t)tx * (512 * 32) + lane_off, wrow,
                         sh_psx + (tx & 3) * 4096 + wx * 512, gco, bq);
            asm volatile("bar.sync 2, 256;" ::: "memory");
            if (tid == 0) { __threadfence_block(); *produced = tx + 1; }
        }
    } else {
        // ============ h-consumer group (warps 8-15, HIGH arbiter priority) ==========
        const int htid = tid - 256;          // 0..255 within h-group
        const int wh   = w - 8;              // 0..7
        const int kb   = wh * 64;
        const float* wrow = sh_w + kb * 16 + gco * 4;
        const int lane_off = kb * 32 + bq * 4;

        const int g_jj = htid >> 5;          // phase B mapping (htid<128)
        const int g_b  = htid & 31;

        for (int t = 0; t < TT; ++t) {
            const float* hT_r = g_hT[t & 1];
            float*       hT_w = g_hT[(t + 1) & 1];

            // ---- h-GEMM (step t) ----
            gemm_slice64(hT_r + lane_off, wrow, sh_ps + wh * 512, gco, bq);
            asm volatile("bar.sync 1, 256;" ::: "memory");

            // ---- wait for x partials of step t ----
            while (*produced < t + 1) __nanosleep(32);
            __threadfence_block();

            // ---- gates phase A (256 h-threads, 2 items each) ----
            {
                const float* px = sh_psx + (t & 3) * 4096;
#pragma unroll
                for (int it = 0; it < 2; it++) {
                    const int item = htid + it * 256;
                    const int gc = item >> 5;
                    const int b  = item & 31;
                    const int off = gc * 32 + b;
                    float s = sh_bias[gc];
#pragma unroll
                    for (int s8 = 0; s8 < 8; s8++)
                        s += sh_ps[s8 * 512 + off];
#pragma unroll
                    for (int s8 = 0; s8 < 8; s8++)
                        s += px[s8 * 512 + off];
                    float g;
                    if ((gc >> 2) == 3) g = tanhf(s);
                    else                g = __fdividef(1.0f, 1.0f + __expf(-s));
                    sh_g[off] = g;
                }
            }
            asm volatile("bar.sync 1, 256;" ::: "memory");
            if (htid == 0) { __threadfence_block(); *consumed = t + 1; }

            // ---- gates phase B (128 h-threads): c/h update ----
            if (htid < 128) {
                const int jj = g_jj, b = g_b;
                float it = sh_g[(0 * 4 + jj) * 32 + b];
                float ft = sh_g[(1 * 4 + jj) * 32 + b];
                float ot = sh_g[(2 * 4 + jj) * 32 + b];
                float gt = sh_g[(3 * 4 + jj) * 32 + b];
                float cn = ft * sh_c[jj * 32 + b] + it * gt;
                float hn = ot * tanhf(cn);
                sh_c[jj * 32 + b] = cn;
                sh_ho[b * 4 + jj] = hn;
                hT_w[(jc + jj) * BB + b] = hn;     // coalesced 128B per jj
            }
            asm volatile("bar.sync 1, 256;" ::: "memory");

            // ---- grid barrier: release arrival; releaser skips its poll ----
            bool releaser = false;
            if (htid == 0) {
                unsigned a;
                asm volatile("atom.release.gpu.global.add.u32 %0, [%1], %2;"
                             : "=r"(a) : "l"(bar_count), "r"(1u) : "memory");
                if (a == (unsigned)(GRID_P - 1)) {
                    releaser = true;
                    *bar_count = 0;
                    asm volatile("st.release.gpu.global.u32 [%0], %1;"
                                 :: "l"(bar_phase), "r"((unsigned)(t + 1)) : "memory");
                }
            }
            if (htid < 32) {
                int b = htid;
                *(float4*)(out + ((size_t)b * TT + t) * HH + jc) = *(float4*)(sh_ho + b * 4);
            }
            if (htid == 0 && !releaser) {
                unsigned ph;
                for (;;) {
                    asm volatile("ld.acquire.gpu.global.u32 %0, [%1];"
                                 : "=r"(ph) : "l"(bar_phase) : "memory");
                    if ((int)ph > t) break;
                    __nanosleep(32);
                }
            }
            asm volatile("bar.sync 1, 256;" ::: "memory");
        }

        // ---- final (h_t, c_t) tail ----
        if (write_tail && htid < 128) {
            const int jj = g_jj, b = g_b;
            const size_t tail = (size_t)BB * TT * HH;
            out[tail + (size_t)b * HH + jc + jj]                   = sh_ho[b * 4 + jj];
            out[tail + (size_t)BB * HH + (size_t)b * HH + jc + jj] = sh_c[jj * 32 + b];
        }
    }
}

// ---------------- launch ----------------
extern "C" void kernel_launch(void* const* d_in, const int* in_sizes, int n_in,
                              void* d_out, int out_size) {
    const float* x   = (const float*)d_in[0];
    const float* h0  = (const float*)d_in[1];
    const float* c0  = (const float*)d_in[2];
    const float* Wii = (const float*)d_in[3];
    const float* Wif = (const float*)d_in[4];
    const float* Wio = (const float*)d_in[5];
    const float* Wig = (const float*)d_in[6];
    const float* Whi = (const float*)d_in[7];
    const float* Whf = (const float*)d_in[8];
    const float* Who = (const float*)d_in[9];
    const float* Whg = (const float*)d_in[10];
    const float* bi  = (const float*)d_in[11];
    const float* bf_ = (const float*)d_in[12];
    const float* bo  = (const float*)d_in[13];
    const float* bg  = (const float*)d_in[14];
    float* out = (float*)d_out;

    const size_t prep_smem = (size_t)32 * XPAD * sizeof(float);
    const size_t smem_bytes = SH_TOTAL_FLOATS * sizeof(float);
    cudaFuncSetAttribute(prep_kernel,
                         cudaFuncAttributeMaxDynamicSharedMemorySize,
                         (int)prep_smem);
    cudaFuncSetAttribute(lstm_fused_kernel,
                         cudaFuncAttributeMaxDynamicSharedMemorySize,
                         (int)smem_bytes);

    const long long tail = (long long)BB * TT * HH;
    const int write_tail = ((long long)out_size >= tail + 2LL * BB * HH) ? 1 : 0;

    prep_kernel<<<TT, 512, prep_smem>>>(x, h0);
    lstm_fused_kernel<<<GRID_P, 512, smem_bytes>>>(
        Whi, Whf, Who, Whg, Wii, Wif, Wio, Wig,
        bi, bf_, bo, bg, c0, out, write_tail);
}